// round 16
// baseline (speedup 1.0000x reference)
#include <cuda_runtime.h>
#include <cstdint>

// SparseStateAggregator, block-parallel T=8, 4-CTA cluster (256 cols per CTA),
// bulk-DMA all-gather with SPLIT shipping: dots of block m+1 ship right after
// stage B (a full D+E of drain slack); only the 32B exact-norm refresh ships at
// iteration end. Depth-4 mbar/recv/staging rings make the early ship phase-safe.

#define D_DIM   1024
#define M_ST    64
#define RANKS   4
#define COLS    256
#define CP      260      // padded centroid/state row stride (floats)
#define T       8
#define TPB     256
#define THRESH_F 0.9f
#define EPS_F   1e-12f
#define NSHIP   584      // 64 rows x 9 (8 dots + pad) + 8 row-norm refreshes
#define SHIP_BYTES 2336
#define DOTS_BYTES 2304
#define TX_BYTES   (RANKS * SHIP_BYTES)

#define OFF_MBAR 0        // 4 x u64 mbarriers (depth-4 ring, tx-based)
#define OFF_GSH  32       // 128 floats: Gram of current block
#define OFF_SUM  544      // 584 floats: rank-summed partials
#define OFF_STG  2880     // 4 x 2336 B staging (16B aligned)
#define OFF_KBUF 12224    // 2 x 8 x 260 floats
#define OFF_VBUF 28864    // 2 x 8 x 256 floats
#define OFF_RECV 45248    // 4 x 4 x 584 floats (16B aligned)
#define OFF_CENT 82624    // 64 x 260 floats
#define OFF_STAT 149184   // 64 x 260 floats
#define SMEM_BYTES 215744

__device__ float g_gram[8 * 512 * 128];   // [b*NB+m][j*16+i]

static __device__ __forceinline__ uint32_t smem_u32(const void* p) {
    uint32_t a;
    asm("{ .reg .u64 t; cvta.to.shared.u64 t, %1; cvt.u32.u64 %0, t; }" : "=r"(a) : "l"(p));
    return a;
}
static __device__ __forceinline__ uint32_t mapa_rank(uint32_t addr, uint32_t rank) {
    uint32_t ra;
    asm("mapa.shared::cluster.u32 %0, %1, %2;" : "=r"(ra) : "r"(addr), "r"(rank));
    return ra;
}
static __device__ __forceinline__ void mbar_init(uint32_t addr, uint32_t cnt) {
    asm volatile("mbarrier.init.shared.b64 [%0], %1;" :: "r"(addr), "r"(cnt) : "memory");
}
static __device__ __forceinline__ void mbar_arrive_local(uint32_t addr) {
    asm volatile("mbarrier.arrive.shared.b64 _, [%0];" :: "r"(addr) : "memory");
}
static __device__ __forceinline__ void mbar_arrive_expect_tx(uint32_t addr, uint32_t bytes) {
    asm volatile("mbarrier.arrive.expect_tx.shared.b64 _, [%0], %1;"
                 :: "r"(addr), "r"(bytes) : "memory");
}
static __device__ __forceinline__ void bulk_copy_peer(uint32_t dst_cluster, uint32_t src_cta,
                                                      uint32_t bytes, uint32_t mbar_cluster) {
    asm volatile("cp.async.bulk.shared::cluster.shared::cta.mbarrier::complete_tx::bytes "
                 "[%0], [%1], %2, [%3];"
                 :: "r"(dst_cluster), "r"(src_cta), "r"(bytes), "r"(mbar_cluster) : "memory");
}
static __device__ __forceinline__ void fence_proxy_async_shared() {
    asm volatile("fence.proxy.async.shared::cta;" ::: "memory");
}
static __device__ __forceinline__ void mbar_wait_cluster(uint32_t mbar, uint32_t parity) {
    asm volatile(
        "{\n\t.reg .pred P1;\n\t"
        "LAB_WAIT_%=:\n\t"
        "mbarrier.try_wait.parity.acquire.cluster.shared::cta.b64 P1, [%0], %1;\n\t"
        "@!P1 bra LAB_WAIT_%=;\n\t}\n"
        :: "r"(mbar), "r"(parity) : "memory");
}
static __device__ __forceinline__ void cluster_sync_all() {
    asm volatile("barrier.cluster.arrive.aligned;" ::: "memory");
    asm volatile("barrier.cluster.wait.aligned;" ::: "memory");
}
static __device__ __forceinline__ unsigned om(float f) {
    unsigned u = __float_as_uint(f);
    return ((int)u < 0) ? ~u : (u | 0x80000000u);
}
static __device__ __forceinline__ float unom(unsigned u) {
    return ((int)u < 0) ? __uint_as_float(u & 0x7fffffffu) : __uint_as_float(~u);
}
static __device__ __forceinline__ unsigned redux_max_u32(unsigned v) {
    unsigned r;
    asm("redux.sync.max.u32 %0, %1, 0xffffffff;" : "=r"(r) : "r"(v));
    return r;
}
static __device__ __forceinline__ void ffma2(float2& acc, float2 a, float2 b) {
    unsigned long long au = *reinterpret_cast<const unsigned long long*>(&a);
    unsigned long long bu = *reinterpret_cast<const unsigned long long*>(&b);
    unsigned long long cu = *reinterpret_cast<unsigned long long*>(&acc);
    asm("fma.rn.f32x2 %0, %1, %2, %0;" : "+l"(cu) : "l"(au), "l"(bu));
    *reinterpret_cast<unsigned long long*>(&acc) = cu;
}

// ---- Gram precompute: G[b,m][j*16+i] = dot(k_{mT+j}, k_{(m-1)T+i}) for i<8,
//      dot(k_{mT+j}, k_{mT+i-8}) for i>=8 (full 1024-dim). One block per (b,m). ----
__global__ void __launch_bounds__(256) gram_kernel(const float* __restrict__ keys,
                                                   int S, int NB) {
    const int blk = blockIdx.x;
    const int m = blk % NB, b = blk / NB;
    const int j = threadIdx.x >> 5, lane = threadIdx.x & 31;
    const float4* kj = (const float4*)(keys + ((size_t)b * S + m * T + j) * D_DIM);
    float4 a[8];
    #pragma unroll
    for (int s = 0; s < 8; ++s) a[s] = kj[s * 32 + lane];
    #pragma unroll
    for (int i = 0; i < 16; ++i) {
        const int ti = (i < 8) ? ((m - 1) * T + i) : (m * T + i - 8);
        float g = 0.0f;
        if (ti >= 0) {
            const float4* kc = (const float4*)(keys + ((size_t)b * S + ti) * D_DIM);
            #pragma unroll
            for (int s = 0; s < 8; ++s) {
                const float4 c = kc[s * 32 + lane];
                g += a[s].x * c.x + a[s].y * c.y + a[s].z * c.z + a[s].w * c.w;
            }
            #pragma unroll
            for (int off = 16; off; off >>= 1)
                g += __shfl_xor_sync(0xffffffffu, g, off);
        }
        if (lane == 0) g_gram[(size_t)blk * 128 + j * 16 + i] = g;
    }
}

__global__ void __cluster_dims__(RANKS, 1, 1) __launch_bounds__(TPB, 1)
sparse_agg_kernel(const float* __restrict__ keys,
                  const float* __restrict__ values,
                  float* __restrict__ out, int S, int NB)
{
    extern __shared__ unsigned char sm[];
    const uint32_t sbase = smem_u32(sm);

    const int tid  = threadIdx.x;
    const int wid  = tid >> 5;
    const int lane = tid & 31;
    const int rank = blockIdx.x & (RANKS - 1);
    const int b    = blockIdx.x / RANKS;
    const int c0   = rank * COLS;

    const float* kb = keys   + (size_t)b * S * D_DIM + c0;
    const float* vb = values + (size_t)b * S * D_DIM + c0;

    float* gsh   = (float*)(sm + OFF_GSH);
    float* summed= (float*)(sm + OFF_SUM);
    float* stg   = (float*)(sm + OFF_STG);
    float* kbuf  = (float*)(sm + OFF_KBUF);
    float* vbuf  = (float*)(sm + OFF_VBUF);
    float* recvf = (float*)(sm + OFF_RECV);
    float* cent  = (float*)(sm + OFF_CENT);
    float* stat  = (float*)(sm + OFF_STAT);

    // ---- init ----
    for (int i = tid; i < M_ST * CP; i += TPB) { cent[i] = 0.0f; stat[i] = 0.0f; }
    for (int i = tid; i < 4 * RANKS * NSHIP; i += TPB) recvf[i] = 0.0f;
    if (tid == 0) {
        #pragma unroll
        for (int q = 0; q < 4; ++q) mbar_init(sbase + OFF_MBAR + 8u * q, 1);
        // block 0: recv pre-zeroed -> complete phase now
        mbar_arrive_local(sbase + OFF_MBAR + 0);
        // blocks 1..3: arm tx expectations before any ship
        #pragma unroll
        for (int q = 1; q < 4; ++q)
            mbar_arrive_expect_tx(sbase + OFF_MBAR + 8u * q, TX_BYTES);
    }
    // preload blocks 0,1 into kbuf/vbuf (token = tid>>5, 2 float4 cols each)
    {
        const int i2 = tid >> 5, c2 = (tid & 31) * 8;
        #pragma unroll
        for (int blk = 0; blk < 2; ++blk) if (blk < NB) {
            const float4 k0 = *(const float4*)(kb + (size_t)(blk * T + i2) * D_DIM + c2);
            const float4 k1 = *(const float4*)(kb + (size_t)(blk * T + i2) * D_DIM + c2 + 4);
            const float4 v0 = *(const float4*)(vb + (size_t)(blk * T + i2) * D_DIM + c2);
            const float4 v1 = *(const float4*)(vb + (size_t)(blk * T + i2) * D_DIM + c2 + 4);
            *(float4*)(kbuf + blk * T * CP + i2 * CP + c2) = k0;
            *(float4*)(kbuf + blk * T * CP + i2 * CP + c2 + 4) = k1;
            *(float4*)(vbuf + blk * T * COLS + i2 * COLS + c2) = v0;
            *(float4*)(vbuf + blk * T * COLS + i2 * COLS + c2 + 4) = v1;
        }
    }
    __syncthreads();
    cluster_sync_all();   // mbarrier inits + expects visible before any bulk copy

    // ---- per-lane persistent state (bit-identical across warps/CTAs) ----
    int   K_reg = 0;
    float cnt0 = 0.0f, cnt1 = 0.0f;    // counts[lane], counts[lane+32]
    float cn2a = 0.0f, cn2b = 0.0f;    // ||centroid||^2
    int   pw[T];
    float pinv[T], dens[T];
    #pragma unroll
    for (int i = 0; i < T; ++i) { pw[i] = -1; pinv[i] = 0.0f; dens[i] = 1.0f; }

    const int csl = lane >> 3;          // B: column slice 0..3 (64 cols each)
    const int stk = lane & 7;           // B: token 0..7

    for (int m = 0; m < NB; ++m) {
        const int buf = m & 1;          // kv ping-pong
        const int bq  = m & 3;          // comm ring slot

        // early register prefetches (latency hidden behind B)
        const float greg = (tid < 128) ? g_gram[(size_t)(b * NB + m) * 128 + tid] : 0.0f;
        float4 kp0 = make_float4(0,0,0,0), kp1 = kp0, vp0 = kp0, vp1 = kp0;
        if (m + 2 < NB) {
            const int i2 = tid >> 5, c2 = (tid & 31) * 8;
            kp0 = *(const float4*)(kb + (size_t)((m + 2) * T + i2) * D_DIM + c2);
            kp1 = *(const float4*)(kb + (size_t)((m + 2) * T + i2) * D_DIM + c2 + 4);
            vp0 = *(const float4*)(vb + (size_t)((m + 2) * T + i2) * D_DIM + c2);
            vp1 = *(const float4*)(vb + (size_t)((m + 2) * T + i2) * D_DIM + c2 + 4);
        }

        // ---- B: dots of block m+1 vs current centroids (broadcast tiling) ----
        // Warp w owns rows 8w..8w+7; lane (csl,stk) = 64-col slice x token.
        if (m + 1 < NB) {
            const float* kpb = kbuf + (buf ^ 1) * T * CP + stk * CP + csl * 64;
            float2 acc[8];
            #pragma unroll
            for (int i = 0; i < 8; ++i) acc[i] = make_float2(0.0f, 0.0f);
            #pragma unroll
            for (int h = 0; h < 2; ++h) {
                float4 kq[8];
                const float4* kp4 = (const float4*)kpb + h * 8;
                #pragma unroll
                for (int q = 0; q < 8; ++q) kq[q] = kp4[q];
                #pragma unroll
                for (int i = 0; i < 8; ++i) {
                    const float4* cr =
                        (const float4*)(cent + (wid * 8 + i) * CP + csl * 64) + h * 8;
                    #pragma unroll
                    for (int q = 0; q < 8; ++q) {
                        const float4 c4 = cr[q];
                        ffma2(acc[i], make_float2(c4.x, c4.y), make_float2(kq[q].x, kq[q].y));
                        ffma2(acc[i], make_float2(c4.z, c4.w), make_float2(kq[q].z, kq[q].w));
                    }
                }
            }
            float p[8];
            #pragma unroll
            for (int i = 0; i < 8; ++i) {
                p[i] = acc[i].x + acc[i].y;
                p[i] += __shfl_xor_sync(0xffffffffu, p[i], 8);
                p[i] += __shfl_xor_sync(0xffffffffu, p[i], 16);
            }
            const float lo = (csl == 0) ? p[0] : (csl == 1) ? p[2] : (csl == 2) ? p[4] : p[6];
            const float hi = (csl == 0) ? p[1] : (csl == 1) ? p[3] : (csl == 2) ? p[5] : p[7];
            const int r0 = wid * 8 + csl * 2;
            float* sd = stg + ((m + 1) & 3) * NSHIP;
            sd[r0 * 9 + stk]       = lo;    // dots layout: [row*9 + token]
            sd[(r0 + 1) * 9 + stk] = hi;
        }
        __syncthreads();   // staging dots complete

        // ---- ship dots EARLY (full D+E of drain slack before consumption) ----
        if (m + 1 < NB && tid == 0) {
            fence_proxy_async_shared();
            const uint32_t src  = sbase + OFF_STG + (uint32_t)(((m + 1) & 3) * SHIP_BYTES);
            const uint32_t dsto = sbase + OFF_RECV +
                (uint32_t)((((m + 1) & 3) * RANKS + rank) * SHIP_BYTES);
            const uint32_t mbo  = sbase + OFF_MBAR + (uint32_t)(((m + 1) & 3) * 8);
            #pragma unroll
            for (int r = 0; r < RANKS; ++r)
                bulk_copy_peer(mapa_rank(dsto, (uint32_t)r), src, DOTS_BYTES,
                               mapa_rank(mbo, (uint32_t)r));
        }

        // ---- wait for block m bytes ----
        mbar_wait_cluster(sbase + OFF_MBAR + (uint32_t)(bq * 8),
                          (uint32_t)((m >> 2) & 1));
        if (tid == 0 && m + 4 < NB)   // re-arm ring slot for block m+4
            mbar_arrive_expect_tx(sbase + OFF_MBAR + (uint32_t)(bq * 8), TX_BYTES);

        // ---- C: reduce rank partials (fixed order -> bit-identical) ----
        {
            const float* rv = recvf + bq * RANKS * NSHIP;
            for (int i = tid; i < NSHIP; i += TPB) {
                float s = 0.0f;
                #pragma unroll
                for (int r = 0; r < RANKS; ++r) s += rv[r * NSHIP + i];
                summed[i] = s;
            }
            if (tid < 128) gsh[tid] = greg;
        }
        __syncthreads();

        // ---- D: all warps redundantly decide the 8 tokens of block m ----
        {
            float da[T], db[T];
            #pragma unroll
            for (int j = 0; j < T; ++j) {
                da[j] = summed[lane * 9 + j];
                db[j] = summed[(lane + 32) * 9 + j];
            }
            // refresh exact norms + correct dots for prev block's 8 updates
            #pragma unroll
            for (int i = 0; i < T; ++i) {
                const int w = pw[i];
                if (w >= 0) {
                    const int ps = w & 63, pc = w >> 8;
                    const float pv = pinv[i], pa = 1.0f - pv;
                    if (ps < 32) {
                        if (lane == ps) {
                            cn2a = summed[576 + i];
                            #pragma unroll
                            for (int j = 0; j < T; ++j) {
                                const float g = gsh[j * 16 + i];
                                da[j] = pc ? g : pa * da[j] + pv * g;
                            }
                        }
                    } else {
                        if (lane == ps - 32) {
                            cn2b = summed[576 + i];
                            #pragma unroll
                            for (int j = 0; j < T; ++j) {
                                const float g = gsh[j * 16 + i];
                                db[j] = pc ? g : pa * db[j] + pv * g;
                            }
                        }
                    }
                }
            }
            // sequential decisions with intra-block corrections
            #pragma unroll
            for (int j = 0; j < T; ++j) {
                const float kn2 = gsh[j * 16 + 8 + j];
                const float rk = rsqrtf(kn2 + EPS_F);
                const float v1 = (cnt0 > 0.0f) ? da[j] * rsqrtf(cn2a + EPS_F) * rk : -3.0e38f;
                const float v2 = (cnt1 > 0.0f) ? db[j] * rsqrtf(cn2b + EPS_F) * rk : -3.0e38f;
                const unsigned u1 = om(v1), u2 = om(v2);
                const unsigned gm = redux_max_u32(u1 > u2 ? u1 : u2);
                const unsigned b1 = __ballot_sync(0xffffffffu, u1 == gm);
                const unsigned b2 = __ballot_sync(0xffffffffu, u2 == gm);
                const int bi = b1 ? (__ffs(b1) - 1) : (32 + __ffs(b2) - 1);
                const float bv = unom(gm);
                const int create = (K_reg == 0) || (bv < THRESH_F && K_reg < M_ST);
                const int slot = create ? K_reg : bi;
                const int sl = slot & 31;
                const float c0s = __shfl_sync(0xffffffffu, cnt0, sl);
                const float c1s = __shfl_sync(0xffffffffu, cnt1, sl);
                const float denom = ((slot < 32) ? c0s : c1s) + 1.0f;
                const float inv = 1.0f / denom, aa = 1.0f - inv;
                if (lane == sl) {
                    if (slot < 32) {
                        cnt0 = create ? 1.0f : denom;
                        cn2a = create ? kn2
                             : aa * aa * cn2a + 2.0f * aa * inv * da[j] + inv * inv * kn2;
                    } else {
                        cnt1 = create ? 1.0f : denom;
                        cn2b = create ? kn2
                             : aa * aa * cn2b + 2.0f * aa * inv * db[j] + inv * inv * kn2;
                    }
                }
                #pragma unroll
                for (int jj = j + 1; jj < T; ++jj) {
                    const float g = gsh[jj * 16 + 8 + j];
                    if (lane == sl) {
                        if (slot < 32) da[jj] = create ? g : aa * da[jj] + inv * g;
                        else           db[jj] = create ? g : aa * db[jj] + inv * g;
                    }
                }
                K_reg += create;
                pw[j] = slot | (create << 8);
                pinv[j] = inv;
                dens[j] = denom;
            }
        }

        // ---- E: apply 8 updates, 256 cols each (reference-exact form) ----
        #pragma unroll
        for (int j = 0; j < T; ++j) {
            const int slot = pw[j] & 63, create = pw[j] >> 8;
            float* cp = cent + slot * CP + tid;
            const float k = kbuf[buf * T * CP + j * CP + tid];
            const float c = *cp;
            *cp = create ? k : c + (k - c) / dens[j];
        }
        #pragma unroll
        for (int j = 0; j < T; ++j) {
            const int slot = pw[j] & 63, create = pw[j] >> 8;
            float* sp = stat + slot * CP + tid;
            const float v = vbuf[buf * T * COLS + j * COLS + tid];
            const float s = *sp;
            *sp = create ? v : s + (v - s) / dens[j];
        }
        __syncthreads();

        // ---- E2: exact post-block row norms (warp w -> update w) -> staging ----
        if (m + 1 < NB) {
            const int myslot = pw[wid] & 63;
            const float4* c4p = (const float4*)(cent + myslot * CP);
            const float4 ca = c4p[lane];
            const float4 cb = c4p[lane + 32];
            float sq = ca.x * ca.x + ca.y * ca.y + ca.z * ca.z + ca.w * ca.w
                     + cb.x * cb.x + cb.y * cb.y + cb.z * cb.z + cb.w * cb.w;
            #pragma unroll
            for (int off = 16; off; off >>= 1)
                sq += __shfl_xor_sync(0xffffffffu, sq, off);
            if (lane == 0) stg[((m + 1) & 3) * NSHIP + 576 + wid] = sq;
        }
        // store prefetched block m+2 into the kv buffer freed by E
        if (m + 2 < NB) {
            const int i2 = tid >> 5, c2 = (tid & 31) * 8;
            *(float4*)(kbuf + buf * T * CP + i2 * CP + c2) = kp0;
            *(float4*)(kbuf + buf * T * CP + i2 * CP + c2 + 4) = kp1;
            *(float4*)(vbuf + buf * T * COLS + i2 * COLS + c2) = vp0;
            *(float4*)(vbuf + buf * T * COLS + i2 * COLS + c2 + 4) = vp1;
        }
        __syncthreads();   // norm staging complete; recv reads done

        // ---- ship norms (32B per peer; completes the TX_BYTES expectation) ----
        if (m + 1 < NB && tid == 0) {
            fence_proxy_async_shared();
            const uint32_t src  = sbase + OFF_STG +
                (uint32_t)(((m + 1) & 3) * SHIP_BYTES + DOTS_BYTES);
            const uint32_t dsto = sbase + OFF_RECV +
                (uint32_t)((((m + 1) & 3) * RANKS + rank) * SHIP_BYTES + DOTS_BYTES);
            const uint32_t mbo  = sbase + OFF_MBAR + (uint32_t)(((m + 1) & 3) * 8);
            #pragma unroll
            for (int r = 0; r < RANKS; ++r)
                bulk_copy_peer(mapa_rank(dsto, (uint32_t)r), src,
                               SHIP_BYTES - DOTS_BYTES, mapa_rank(mbo, (uint32_t)r));
        }
    }

    // ---- flush states ----
    {
        float* ob = out + (size_t)b * M_ST * D_DIM + c0;
        for (int s = 0; s < M_ST; ++s)
            ob[(size_t)s * D_DIM + tid] = stat[s * CP + tid];
    }
    cluster_sync_all();   // keep SMEM alive until peers' in-flight copies settle
}

extern "C" void kernel_launch(void* const* d_in, const int* in_sizes, int n_in,
                              void* d_out, int out_size) {
    const float* keys   = (const float*)d_in[0];
    const float* values = (const float*)d_in[1];
    float* out = (float*)d_out;

    const int B = out_size / (M_ST * D_DIM);
    const int S = in_sizes[0] / (B * D_DIM);
    const int NB = S / T;

    gram_kernel<<<B * NB, 256>>>(keys, S, NB);

    cudaFuncSetAttribute(sparse_agg_kernel,
                         cudaFuncAttributeMaxDynamicSharedMemorySize, SMEM_BYTES);
    sparse_agg_kernel<<<B * RANKS, TPB, SMEM_BYTES>>>(keys, values, out, S, NB);
}

// round 17
// speedup vs baseline: 1.2592x; 1.2592x over previous
#include <cuda_runtime.h>
#include <cstdint>

// SparseStateAggregator, block-parallel T=8, 8-CTA cluster, bulk-DMA all-gather.
// R15 structure (B before wait, broadcast B tiling, ship at end) with stage D
// executed by WARP 0 ONLY (was redundantly run by all 8 warps = half the issue
// budget); per-token results broadcast via a small SMEM params array.

#define D_DIM   1024
#define M_ST    64
#define RANKS   8
#define COLS    128
#define CP      132      // padded row stride (floats)
#define T       8
#define TPB     256
#define THRESH_F 0.9f
#define EPS_F   1e-12f
#define NSHIP   552      // 8 tokens x 68 (64 dots + pad) + 8 row-norm refreshes
#define SHIP_BYTES 2208
#define TX_BYTES   (RANKS * SHIP_BYTES)

#define OFF_MBAR 0        // 2 x u64 mbarriers (depth-2 ring, tx-based)
#define OFF_PAR  16       // 8 x int: slot | create<<8
#define OFF_PARD 48       // 8 x float: denom
#define OFF_GSH  80       // 128 floats: Gram of current block
#define OFF_SUM  592      // 552 floats: rank-summed partials
#define OFF_STG  2800     // 2 x 2208 B staging (16B aligned)
#define OFF_KBUF 7216     // 2 x 8 x 132 floats
#define OFF_VBUF 15664    // 2 x 8 x 128 floats
#define OFF_RECV 23856    // 2 x 8 x 552 floats (16B aligned)
#define OFF_CENT 59184    // 64 x 132 floats
#define OFF_STAT 92976    // 64 x 132 floats
#define SMEM_BYTES 126768

__device__ float g_gram[8 * 512 * 128];   // [b*NB+m][j*16+i]

static __device__ __forceinline__ uint32_t smem_u32(const void* p) {
    uint32_t a;
    asm("{ .reg .u64 t; cvta.to.shared.u64 t, %1; cvt.u32.u64 %0, t; }" : "=r"(a) : "l"(p));
    return a;
}
static __device__ __forceinline__ uint32_t mapa_rank(uint32_t addr, uint32_t rank) {
    uint32_t ra;
    asm("mapa.shared::cluster.u32 %0, %1, %2;" : "=r"(ra) : "r"(addr), "r"(rank));
    return ra;
}
static __device__ __forceinline__ void mbar_init(uint32_t addr, uint32_t cnt) {
    asm volatile("mbarrier.init.shared.b64 [%0], %1;" :: "r"(addr), "r"(cnt) : "memory");
}
static __device__ __forceinline__ void mbar_arrive_local(uint32_t addr) {
    asm volatile("mbarrier.arrive.shared.b64 _, [%0];" :: "r"(addr) : "memory");
}
static __device__ __forceinline__ void mbar_arrive_expect_tx(uint32_t addr, uint32_t bytes) {
    asm volatile("mbarrier.arrive.expect_tx.shared.b64 _, [%0], %1;"
                 :: "r"(addr), "r"(bytes) : "memory");
}
static __device__ __forceinline__ void bulk_copy_peer(uint32_t dst_cluster, uint32_t src_cta,
                                                      uint32_t bytes, uint32_t mbar_cluster) {
    asm volatile("cp.async.bulk.shared::cluster.shared::cta.mbarrier::complete_tx::bytes "
                 "[%0], [%1], %2, [%3];"
                 :: "r"(dst_cluster), "r"(src_cta), "r"(bytes), "r"(mbar_cluster) : "memory");
}
static __device__ __forceinline__ void fence_proxy_async_shared() {
    asm volatile("fence.proxy.async.shared::cta;" ::: "memory");
}
static __device__ __forceinline__ void mbar_wait_cluster(uint32_t mbar, uint32_t parity) {
    asm volatile(
        "{\n\t.reg .pred P1;\n\t"
        "LAB_WAIT_%=:\n\t"
        "mbarrier.try_wait.parity.acquire.cluster.shared::cta.b64 P1, [%0], %1;\n\t"
        "@!P1 bra LAB_WAIT_%=;\n\t}\n"
        :: "r"(mbar), "r"(parity) : "memory");
}
static __device__ __forceinline__ void cluster_sync_all() {
    asm volatile("barrier.cluster.arrive.aligned;" ::: "memory");
    asm volatile("barrier.cluster.wait.aligned;" ::: "memory");
}
static __device__ __forceinline__ unsigned om(float f) {
    unsigned u = __float_as_uint(f);
    return ((int)u < 0) ? ~u : (u | 0x80000000u);
}
static __device__ __forceinline__ float unom(unsigned u) {
    return ((int)u < 0) ? __uint_as_float(u & 0x7fffffffu) : __uint_as_float(~u);
}
static __device__ __forceinline__ unsigned redux_max_u32(unsigned v) {
    unsigned r;
    asm("redux.sync.max.u32 %0, %1, 0xffffffff;" : "=r"(r) : "r"(v));
    return r;
}
static __device__ __forceinline__ void ffma2(float2& acc, float2 a, float2 b) {
    unsigned long long au = *reinterpret_cast<const unsigned long long*>(&a);
    unsigned long long bu = *reinterpret_cast<const unsigned long long*>(&b);
    unsigned long long cu = *reinterpret_cast<unsigned long long*>(&acc);
    asm("fma.rn.f32x2 %0, %1, %2, %0;" : "+l"(cu) : "l"(au), "l"(bu));
    *reinterpret_cast<unsigned long long*>(&acc) = cu;
}

// ---- Gram precompute: G[b,m][j*16+i] = dot(k_{mT+j}, k_{(m-1)T+i}) for i<8,
//      dot(k_{mT+j}, k_{mT+i-8}) for i>=8 (full 1024-dim). One block per (b,m). ----
__global__ void __launch_bounds__(256) gram_kernel(const float* __restrict__ keys,
                                                   int S, int NB) {
    const int blk = blockIdx.x;
    const int m = blk % NB, b = blk / NB;
    const int j = threadIdx.x >> 5, lane = threadIdx.x & 31;
    const float4* kj = (const float4*)(keys + ((size_t)b * S + m * T + j) * D_DIM);
    float4 a[8];
    #pragma unroll
    for (int s = 0; s < 8; ++s) a[s] = kj[s * 32 + lane];
    #pragma unroll
    for (int i = 0; i < 16; ++i) {
        const int ti = (i < 8) ? ((m - 1) * T + i) : (m * T + i - 8);
        float g = 0.0f;
        if (ti >= 0) {
            const float4* kc = (const float4*)(keys + ((size_t)b * S + ti) * D_DIM);
            #pragma unroll
            for (int s = 0; s < 8; ++s) {
                const float4 c = kc[s * 32 + lane];
                g += a[s].x * c.x + a[s].y * c.y + a[s].z * c.z + a[s].w * c.w;
            }
            #pragma unroll
            for (int off = 16; off; off >>= 1)
                g += __shfl_xor_sync(0xffffffffu, g, off);
        }
        if (lane == 0) g_gram[(size_t)blk * 128 + j * 16 + i] = g;
    }
}

__global__ void __cluster_dims__(RANKS, 1, 1) __launch_bounds__(TPB, 1)
sparse_agg_kernel(const float* __restrict__ keys,
                  const float* __restrict__ values,
                  float* __restrict__ out, int S, int NB)
{
    extern __shared__ unsigned char sm[];
    const uint32_t sbase = smem_u32(sm);

    const int tid  = threadIdx.x;
    const int wid  = tid >> 5;
    const int lane = tid & 31;
    const int rank = blockIdx.x & (RANKS - 1);
    const int b    = blockIdx.x >> 3;
    const int c0   = rank * COLS;

    const float* kb = keys   + (size_t)b * S * D_DIM + c0;
    const float* vb = values + (size_t)b * S * D_DIM + c0;

    int*   spar_i = (int*)  (sm + OFF_PAR);
    float* spar_f = (float*)(sm + OFF_PARD);
    float* gsh   = (float*)(sm + OFF_GSH);
    float* summed= (float*)(sm + OFF_SUM);
    float* stg   = (float*)(sm + OFF_STG);
    float* kbuf  = (float*)(sm + OFF_KBUF);
    float* vbuf  = (float*)(sm + OFF_VBUF);
    float* recvf = (float*)(sm + OFF_RECV);
    float* cent  = (float*)(sm + OFF_CENT);
    float* stat  = (float*)(sm + OFF_STAT);

    // ---- init ----
    for (int i = tid; i < M_ST * CP; i += TPB) { cent[i] = 0.0f; stat[i] = 0.0f; }
    for (int i = tid; i < 2 * RANKS * NSHIP; i += TPB) recvf[i] = 0.0f;
    if (tid == 0) {
        mbar_init(sbase + OFF_MBAR + 0, 1);
        mbar_init(sbase + OFF_MBAR + 8, 1);
        // block 0: recv pre-zeroed (dots vs empty centroids) -> complete phase now
        mbar_arrive_local(sbase + OFF_MBAR + 0);
        // block 1: expect 8 bulk copies (posted before cluster_sync -> before any ship)
        mbar_arrive_expect_tx(sbase + OFF_MBAR + 8, TX_BYTES);
    }
    // preload blocks 0,1 into kbuf/vbuf
    {
        const int e = tid * 4, i = e >> 7, c = e & 127;
        #pragma unroll
        for (int blk = 0; blk < 2; ++blk) if (blk < NB) {
            const float4 kv = *(const float4*)(kb + (size_t)(blk * T + i) * D_DIM + c);
            const float4 vv = *(const float4*)(vb + (size_t)(blk * T + i) * D_DIM + c);
            *(float4*)(kbuf + blk * T * CP + i * CP + c) = kv;
            *(float4*)(vbuf + blk * T * COLS + i * COLS + c) = vv;
        }
    }
    __syncthreads();
    cluster_sync_all();   // mbarrier inits + expects visible before any bulk copy

    // ---- warp-0 persistent decision state ----
    int   K_reg = 0;
    float cnt0 = 0.0f, cnt1 = 0.0f;    // counts[lane], counts[lane+32]
    float cn2a = 0.0f, cn2b = 0.0f;    // ||centroid||^2
    int   pw[T];
    float pinv[T];
    #pragma unroll
    for (int i = 0; i < T; ++i) { pw[i] = -1; pinv[i] = 0.0f; }

    const int csl = lane >> 3;          // B: column slice 0..3 (32 cols)
    const int stk = lane & 7;           // B: token 0..7

    for (int m = 0; m < NB; ++m) {
        const int buf = m & 1;

        // early global prefetches (latency hidden behind B)
        const float greg = (tid < 128) ? g_gram[(size_t)(b * NB + m) * 128 + tid] : 0.0f;
        float4 kpre = make_float4(0, 0, 0, 0), vpre = kpre;
        if (m + 2 < NB) {
            const int e = tid * 4, i = e >> 7, c = e & 127;
            kpre = *(const float4*)(kb + (size_t)((m + 2) * T + i) * D_DIM + c);
            vpre = *(const float4*)(vb + (size_t)((m + 2) * T + i) * D_DIM + c);
        }

        // ---- B (BEFORE the wait): dots of block m+1 vs current centroids ----
        // Warp w owns rows 8w..8w+7. Lane (csl, stk): slice csl (32 cols), token stk.
        if (m + 1 < NB) {
            const float4* kp = (const float4*)(kbuf + (buf ^ 1) * T * CP + stk * CP) + csl * 8;
            float4 kq[8];
            #pragma unroll
            for (int q = 0; q < 8; ++q) kq[q] = kp[q];
            float p[8];
            #pragma unroll
            for (int i = 0; i < 8; ++i) {
                const float4* cr = (const float4*)(cent + (wid * 8 + i) * CP) + csl * 8;
                float2 acc = make_float2(0.0f, 0.0f);
                #pragma unroll
                for (int q = 0; q < 8; ++q) {
                    const float4 c4 = cr[q];
                    ffma2(acc, make_float2(c4.x, c4.y), make_float2(kq[q].x, kq[q].y));
                    ffma2(acc, make_float2(c4.z, c4.w), make_float2(kq[q].z, kq[q].w));
                }
                p[i] = acc.x + acc.y;
            }
            #pragma unroll
            for (int i = 0; i < 8; ++i) {   // reduce across the 4 column slices
                p[i] += __shfl_xor_sync(0xffffffffu, p[i], 8);
                p[i] += __shfl_xor_sync(0xffffffffu, p[i], 16);
            }
            const float lo = (csl == 0) ? p[0] : (csl == 1) ? p[2] : (csl == 2) ? p[4] : p[6];
            const float hi = (csl == 0) ? p[1] : (csl == 1) ? p[3] : (csl == 2) ? p[5] : p[7];
            *(float2*)(stg + (buf ^ 1) * NSHIP + stk * 68 + wid * 8 + csl * 2) =
                make_float2(lo, hi);
        }

        // ---- wait for block m bytes (shipped end of iter m-1; drained behind B) ----
        mbar_wait_cluster(sbase + OFF_MBAR + (uint32_t)(buf * 8),
                          (uint32_t)((m >> 1) & 1));
        // re-arm next phase (block m+2) — peers' m+2 ships transitively gated on ours
        if (tid == 0)
            mbar_arrive_expect_tx(sbase + OFF_MBAR + (uint32_t)(buf * 8), TX_BYTES);

        // ---- C: reduce rank partials of block m (fixed order -> bit-identical) ----
        {
            const float* rv = recvf + buf * RANKS * NSHIP;
            for (int i = tid; i < NSHIP; i += TPB) {
                float s = 0.0f;
                #pragma unroll
                for (int r = 0; r < RANKS; ++r) s += rv[r * NSHIP + i];
                summed[i] = s;
            }
            if (tid < 128) gsh[tid] = greg;
        }
        __syncthreads();

        // ---- D: warp 0 ONLY decides the 8 tokens; results -> SMEM params ----
        if (wid == 0) {
            float da[T], db[T];
            #pragma unroll
            for (int j = 0; j < T; ++j) {
                da[j] = summed[j * 68 + lane];
                db[j] = summed[j * 68 + 32 + lane];
            }
            // refresh exact norms + correct dots for prev block's 8 updates
            #pragma unroll
            for (int i = 0; i < T; ++i) {
                const int w = pw[i];
                if (w >= 0) {
                    const int ps = w & 63, pc = w >> 8;
                    const float pv = pinv[i], pa = 1.0f - pv;
                    if (ps < 32) {
                        if (lane == ps) {
                            cn2a = summed[544 + i];
                            #pragma unroll
                            for (int j = 0; j < T; ++j) {
                                const float g = gsh[j * 16 + i];
                                da[j] = pc ? g : pa * da[j] + pv * g;
                            }
                        }
                    } else {
                        if (lane == ps - 32) {
                            cn2b = summed[544 + i];
                            #pragma unroll
                            for (int j = 0; j < T; ++j) {
                                const float g = gsh[j * 16 + i];
                                db[j] = pc ? g : pa * db[j] + pv * g;
                            }
                        }
                    }
                }
            }
            // sequential decisions with intra-block corrections
            #pragma unroll
            for (int j = 0; j < T; ++j) {
                const float kn2 = gsh[j * 16 + 8 + j];
                const float rk = rsqrtf(kn2 + EPS_F);
                const float v1 = (cnt0 > 0.0f) ? da[j] * rsqrtf(cn2a + EPS_F) * rk : -3.0e38f;
                const float v2 = (cnt1 > 0.0f) ? db[j] * rsqrtf(cn2b + EPS_F) * rk : -3.0e38f;
                const unsigned u1 = om(v1), u2 = om(v2);
                const unsigned gm = redux_max_u32(u1 > u2 ? u1 : u2);
                const unsigned b1 = __ballot_sync(0xffffffffu, u1 == gm);
                const unsigned b2 = __ballot_sync(0xffffffffu, u2 == gm);
                const int bi = b1 ? (__ffs(b1) - 1) : (32 + __ffs(b2) - 1);
                const float bv = unom(gm);
                const int create = (K_reg == 0) || (bv < THRESH_F && K_reg < M_ST);
                const int slot = create ? K_reg : bi;
                const int sl = slot & 31;
                const float c0s = __shfl_sync(0xffffffffu, cnt0, sl);
                const float c1s = __shfl_sync(0xffffffffu, cnt1, sl);
                const float denom = ((slot < 32) ? c0s : c1s) + 1.0f;
                const float inv = 1.0f / denom, aa = 1.0f - inv;
                if (lane == sl) {
                    if (slot < 32) {
                        cnt0 = create ? 1.0f : denom;
                        cn2a = create ? kn2
                             : aa * aa * cn2a + 2.0f * aa * inv * da[j] + inv * inv * kn2;
                    } else {
                        cnt1 = create ? 1.0f : denom;
                        cn2b = create ? kn2
                             : aa * aa * cn2b + 2.0f * aa * inv * db[j] + inv * inv * kn2;
                    }
                }
                #pragma unroll
                for (int jj = j + 1; jj < T; ++jj) {
                    const float g = gsh[jj * 16 + 8 + j];
                    if (lane == sl) {
                        if (slot < 32) da[jj] = create ? g : aa * da[jj] + inv * g;
                        else           db[jj] = create ? g : aa * db[jj] + inv * g;
                    }
                }
                K_reg += create;
                pw[j] = slot | (create << 8);
                pinv[j] = inv;
                if (lane == 0) { spar_i[j] = pw[j]; spar_f[j] = denom; }
            }
        }
        __syncthreads();   // params visible to all warps

        // ---- E: apply 8 updates (reference-exact form) ----
        if (tid < 128) {
            #pragma unroll
            for (int j = 0; j < T; ++j) {
                const int w = spar_i[j];
                const int slot = w & 63, create = w >> 8;
                const float dn = spar_f[j];
                float* cp = cent + slot * CP + tid;
                const float k = kbuf[buf * T * CP + j * CP + tid];
                const float c = *cp;
                *cp = create ? k : c + (k - c) / dn;
            }
        } else {
            const int col = tid - 128;
            #pragma unroll
            for (int j = 0; j < T; ++j) {
                const int w = spar_i[j];
                const int slot = w & 63, create = w >> 8;
                const float dn = spar_f[j];
                float* sp = stat + slot * CP + col;
                const float v = vbuf[buf * T * COLS + j * COLS + col];
                const float s = *sp;
                *sp = create ? v : s + (v - s) / dn;
            }
        }
        __syncthreads();

        // ---- E2: exact post-block row norms (warp w -> update w) -> staging ----
        if (m + 1 < NB) {
            const int myslot = spar_i[wid] & 63;
            const float4 c4 = ((const float4*)(cent + myslot * CP))[lane];
            float sq = c4.x * c4.x + c4.y * c4.y + c4.z * c4.z + c4.w * c4.w;
            #pragma unroll
            for (int off = 16; off; off >>= 1)
                sq += __shfl_xor_sync(0xffffffffu, sq, off);
            if (lane == 0) stg[(buf ^ 1) * NSHIP + 544 + wid] = sq;
        }
        // store prefetched block m+2 into the kv buffer freed by E
        if (m + 2 < NB) {
            const int e = tid * 4, i = e >> 7, c = e & 127;
            *(float4*)(kbuf + buf * T * CP + i * CP + c) = kpre;
            *(float4*)(vbuf + buf * T * COLS + i * COLS + c) = vpre;
        }
        __syncthreads();   // staging (dots + norms) complete; all recv reads done

        // ---- ship: 8 async bulk copies (tx-counted at destinations) ----
        if (m + 1 < NB && tid == 0) {
            fence_proxy_async_shared();
            const uint32_t src  = sbase + OFF_STG + (uint32_t)((buf ^ 1) * SHIP_BYTES);
            const uint32_t dsto = sbase + OFF_RECV +
                (uint32_t)(((buf ^ 1) * RANKS + rank) * SHIP_BYTES);
            const uint32_t mbo  = sbase + OFF_MBAR + (uint32_t)((buf ^ 1) * 8);
            #pragma unroll
            for (int r = 0; r < RANKS; ++r)
                bulk_copy_peer(mapa_rank(dsto, (uint32_t)r), src, SHIP_BYTES,
                               mapa_rank(mbo, (uint32_t)r));
        }
    }

    // ---- flush states ----
    {
        const int half = tid >> 7, j = tid & 127;
        float* ob = out + (size_t)b * M_ST * D_DIM + c0;
        for (int s = half * 32; s < half * 32 + 32; ++s)
            ob[(size_t)s * D_DIM + j] = stat[s * CP + j];
    }
    cluster_sync_all();   // keep SMEM alive until peers' in-flight copies settle
}

extern "C" void kernel_launch(void* const* d_in, const int* in_sizes, int n_in,
                              void* d_out, int out_size) {
    const float* keys   = (const float*)d_in[0];
    const float* values = (const float*)d_in[1];
    float* out = (float*)d_out;

    const int B = out_size / (M_ST * D_DIM);
    const int S = in_sizes[0] / (B * D_DIM);
    const int NB = S / T;

    gram_kernel<<<B * NB, 256>>>(keys, S, NB);

    cudaFuncSetAttribute(sparse_agg_kernel,
                         cudaFuncAttributeMaxDynamicSharedMemorySize, SMEM_BYTES);
    sparse_agg_kernel<<<B * RANKS, TPB, SMEM_BYTES>>>(keys, values, out, S, NB);
}